// round 10
// baseline (speedup 1.0000x reference)
#include <cuda_runtime.h>
#include <cstdint>
#include <math.h>

#define NN 100000          // nodes
#define EE 1600000         // edges (max)
#define HF 64              // hidden feats
#define HF3 192            // (D+1)*HF
#define NG (3 * NN)        // (fam,node) groups
typedef unsigned long long ull;

// ---------------- scratch (device globals; no allocations allowed) ----------
__device__ __align__(128) float g_h  [NN * HF];        // MLP output h
__device__ __align__(128) float g_L1 [3 * NN * HF];    // per-family L^1 h (also layer-1 scratch)
__device__ __align__(128) float g_hf [NN * HF3];       // concatenated features
__device__ float g_dinv[NG];
__device__ int   g_deg [NG];
__device__ int   g_off [NG];           // CSR offsets
__device__ int   g_cur [NG];           // fill cursors
__device__ int   g_bsum[256];          // scan block sums
__device__ __align__(16) int2 g_ecsr[EE];  // CSR: (src, dinv-bits) per slot
__device__ unsigned char g_cls[EE];
__device__ unsigned int g_histA[2 * 65536];   // pass-A 16-bit histograms (neg,pos)
__device__ unsigned int g_histB[4 * 65536];   // pass-B histograms (4 targets)
__device__ unsigned int g_prefix[4];   // after scanA: top-16 prefix<<16; after scanB: full key
__device__ int g_rank[4];
__device__ double g_frac[2];
__device__ float g_thr[2];

// ---------------- helpers ----------------------------------------------------
__device__ __forceinline__ unsigned f2u(float f) {
    unsigned u = __float_as_uint(f);
    return (u & 0x80000000u) ? ~u : (u ^ 0x80000000u);
}
__device__ __forceinline__ float u2f(unsigned k) {
    unsigned u = (k & 0x80000000u) ? (k ^ 0x80000000u) : ~k;
    return __uint_as_float(u);
}
#define FMA2(acc, a, w) asm("fma.rn.f32x2 %0, %1, %2, %0;" : "+l"(acc) : "l"(a), "l"(w))
__device__ __forceinline__ ull packdup(float a) {
    ull r;
    asm("mov.b64 %0, {%1, %1};" : "=l"(r) : "r"(__float_as_uint(a)));
    return r;
}
__device__ __forceinline__ float2 unpack2(ull v) {
    unsigned lo, hi;
    asm("mov.b64 {%0, %1}, %2;" : "=r"(lo), "=r"(hi) : "l"(v));
    return make_float2(__uint_as_float(lo), __uint_as_float(hi));
}

// ---------------- init --------------------------------------------------------
__global__ void k_init() {
    int t = blockIdx.x * blockDim.x + threadIdx.x;
    int stride = gridDim.x * blockDim.x;
    for (int i = t; i < 2 * 65536; i += stride) g_histA[i] = 0;
    for (int i = t; i < 4 * 65536; i += stride) g_histB[i] = 0;
    for (int i = t; i < NG; i += stride) g_deg[i] = 0;
}

// ---------------- quantile: 2-pass 16-bit radix select ------------------------
__global__ void __launch_bounds__(256) k_histA(const float* __restrict__ ep, int E) {
    int t = blockIdx.x * blockDim.x + threadIdx.x;
    int stride = gridDim.x * blockDim.x;
    for (int i = t; i < E; i += stride) {
        float x = ep[i];
        unsigned key = f2u(x);
        int s = (x <= 0.f) ? 0 : 1;
        atomicAdd(&g_histA[s * 65536 + (key >> 16)], 1u);
    }
}

// single block, 1024 threads: find top-16 prefix + residual rank for 4 targets
__global__ void __launch_bounds__(1024) k_scanA() {
    __shared__ int part[2][1024];
    __shared__ int ranks[4];
    int tid = threadIdx.x;
    int own[2];
    for (int s = 0; s < 2; s++) {
        int sum = 0;
        const unsigned* h = g_histA + s * 65536 + tid * 64;
        #pragma unroll 8
        for (int i = 0; i < 64; i++) sum += (int)h[i];
        own[s] = sum;
        part[s][tid] = sum;
    }
    __syncthreads();
    for (int d = 1; d < 1024; d <<= 1) {
        int a0 = (tid >= d) ? part[0][tid - d] : 0;
        int a1 = (tid >= d) ? part[1][tid - d] : 0;
        __syncthreads();
        part[0][tid] += a0; part[1][tid] += a1;
        __syncthreads();
    }
    if (tid == 0) {
        long long nn = part[0][1023], np = part[1][1023];
        double idxn = 0.2 * (double)(nn - 1);
        double fln = floor(idxn);
        g_frac[0] = idxn - fln;
        long long lon = (long long)fln;
        long long hin = lon + 1; if (hin > nn - 1) hin = nn - 1;
        ranks[0] = (int)lon; ranks[1] = (int)hin;
        double idxp = 0.8 * (double)(np - 1);
        double flp = floor(idxp);
        g_frac[1] = idxp - flp;
        long long lop = (long long)flp;
        long long hip = lop + 1; if (hip > np - 1) hip = np - 1;
        ranks[2] = (int)lop; ranks[3] = (int)hip;
    }
    __syncthreads();
    for (int tg = 0; tg < 4; tg++) {
        int s = tg >> 1;
        int r = ranks[tg];
        int excl = part[s][tid] - own[s];
        if (r >= excl && r < excl + own[s]) {
            int rem = r - excl;
            const unsigned* h = g_histA + s * 65536 + tid * 64;
            for (int i = 0; i < 64; i++) {
                unsigned c = h[i];
                if ((unsigned)rem < c) {
                    g_prefix[tg] = ((unsigned)(tid * 64 + i)) << 16;
                    g_rank[tg] = rem;
                    break;
                }
                rem -= (int)c;
            }
        }
    }
}

__global__ void __launch_bounds__(256) k_histB(const float* __restrict__ ep, int E) {
    unsigned p0 = g_prefix[0], p1 = g_prefix[1], p2 = g_prefix[2], p3 = g_prefix[3];
    int t = blockIdx.x * blockDim.x + threadIdx.x;
    int stride = gridDim.x * blockDim.x;
    for (int i = t; i < E; i += stride) {
        float x = ep[i];
        unsigned key = f2u(x);
        unsigned top = key & 0xFFFF0000u;
        unsigned lo = key & 0xFFFFu;
        if (x <= 0.f) {
            if (top == p0) atomicAdd(&g_histB[0 * 65536 + lo], 1u);
            if (top == p1) atomicAdd(&g_histB[1 * 65536 + lo], 1u);
        } else {
            if (top == p2) atomicAdd(&g_histB[2 * 65536 + lo], 1u);
            if (top == p3) atomicAdd(&g_histB[3 * 65536 + lo], 1u);
        }
    }
}

// single block: resolve low 16 bits for each target, then compute thresholds
__global__ void __launch_bounds__(1024) k_scanB() {
    __shared__ int part[1024];
    __shared__ unsigned keys[4];
    int tid = threadIdx.x;
    for (int tg = 0; tg < 4; tg++) {
        int sum = 0;
        const unsigned* h = g_histB + tg * 65536 + tid * 64;
        #pragma unroll 8
        for (int i = 0; i < 64; i++) sum += (int)h[i];
        int own = sum;
        part[tid] = sum;
        __syncthreads();
        for (int d = 1; d < 1024; d <<= 1) {
            int a = (tid >= d) ? part[tid - d] : 0;
            __syncthreads();
            part[tid] += a;
            __syncthreads();
        }
        int r = g_rank[tg];
        int excl = part[tid] - own;
        if (r >= excl && r < excl + own) {
            int rem = r - excl;
            for (int i = 0; i < 64; i++) {
                unsigned c = h[i];
                if ((unsigned)rem < c) {
                    keys[tg] = g_prefix[tg] | (unsigned)(tid * 64 + i);
                    break;
                }
                rem -= (int)c;
            }
        }
        __syncthreads();
    }
    if (tid == 0) {
        float vlo = u2f(keys[0]), vhi = u2f(keys[1]);
        g_thr[0] = (float)((double)vlo + g_frac[0] * ((double)vhi - (double)vlo));
        vlo = u2f(keys[2]); vhi = u2f(keys[3]);
        g_thr[1] = (float)((double)vlo + g_frac[1] * ((double)vhi - (double)vlo));
    }
}

// ---------------- classify + degrees -----------------------------------------
__global__ void k_classify(const float* __restrict__ ep, const int* __restrict__ dst, int E) {
    int i = blockIdx.x * blockDim.x + threadIdx.x;
    if (i >= E) return;
    float x = ep[i];
    float tn = g_thr[0], tp = g_thr[1];
    int c = (x > tp) ? 0 : ((x < tn) ? 2 : 1);   // 0=pos, 1=unk, 2=neg
    g_cls[i] = (unsigned char)c;
    atomicAdd(&g_deg[c * NN + dst[i]], 1);
}

// ---------------- exclusive scan of g_deg -> g_off, fused dinv ----------------
__global__ void __launch_bounds__(256) k_scan1() {
    __shared__ int ssum[256];
    int tid = threadIdx.x;
    int base = blockIdx.x * 2048 + tid * 8;
    int v[8]; int s = 0;
    #pragma unroll
    for (int i = 0; i < 8; i++) {
        v[i] = (base + i < NG) ? g_deg[base + i] : 0;
        s += v[i];
    }
    ssum[tid] = s;
    __syncthreads();
    #pragma unroll
    for (int d = 1; d < 256; d <<= 1) {
        int t = (tid >= d) ? ssum[tid - d] : 0;
        __syncthreads();
        ssum[tid] += t;
        __syncthreads();
    }
    int run = ssum[tid] - s;
    #pragma unroll
    for (int i = 0; i < 8; i++) {
        if (base + i < NG) g_off[base + i] = run;
        run += v[i];
    }
    if (tid == 255) g_bsum[blockIdx.x] = ssum[255];
}

__global__ void k_scan2(int nblk) {
    if (threadIdx.x == 0) {
        int acc = 0;
        for (int i = 0; i < nblk; i++) {
            int v = g_bsum[i];
            g_bsum[i] = acc;
            acc += v;
        }
    }
}

__global__ void k_scan3() {
    int i = blockIdx.x * blockDim.x + threadIdx.x;
    if (i >= NG) return;
    int o = g_off[i] + g_bsum[i >> 11];
    g_off[i] = o;
    g_cur[i] = o;
    int d = g_deg[i];
    if (d < 1) d = 1;
    g_dinv[i] = 1.0f / sqrtf((float)d);
}

// ---------------- CSR fill (packed records) -----------------------------------
__global__ void k_fill(const int* __restrict__ src, const int* __restrict__ dst, int E) {
    int i = blockIdx.x * blockDim.x + threadIdx.x;
    if (i >= E) return;
    int c = (int)g_cls[i];
    int s = src[i];
    int slot = atomicAdd(&g_cur[c * NN + dst[i]], 1);
    int2 rec;
    rec.x = s;
    rec.y = __float_as_int(g_dinv[c * NN + s]);
    g_ecsr[slot] = rec;
}

// ---------------- gather aggregation (unrolled, MLP=4) ------------------------
#define GACC(e) { float sc = __int_as_float((e).y); \
    const float4 v = *(const float4*)(f + (size_t)(e).x * HF + lane4); \
    acc.x = fmaf(sc, v.x, acc.x); acc.y = fmaf(sc, v.y, acc.y); \
    acc.z = fmaf(sc, v.z, acc.z); acc.w = fmaf(sc, v.w, acc.w); }

__global__ void __launch_bounds__(256) k_aggL1() {
    int t = blockIdx.x * blockDim.x + threadIdx.x;
    int gi = t >> 4, lane4 = (t & 15) * 4;
    if (gi >= NG) return;
    int fam = gi / NN;
    int node = gi - fam * NN;
    int deg = g_deg[gi];
    const int2* ec = g_ecsr + g_off[gi];
    const float* f = g_h;
    float4 acc = make_float4(0.f, 0.f, 0.f, 0.f);
    int j = 0;
    for (; j + 4 <= deg; j += 4) {
        int2 e0 = ec[j], e1 = ec[j + 1], e2 = ec[j + 2], e3 = ec[j + 3];
        GACC(e0); GACC(e1); GACC(e2); GACC(e3);
    }
    for (; j < deg; j++) { int2 e = ec[j]; GACC(e); }
    float dv = g_dinv[gi];
    float4 h = *(const float4*)(g_h + (size_t)node * HF + lane4);
    float4 o;
    o.x = h.x - dv * acc.x; o.y = h.y - dv * acc.y;
    o.z = h.z - dv * acc.z; o.w = h.w - dv * acc.w;
    *(float4*)(g_L1 + ((size_t)fam * NN + node) * HF + lane4) = o;
}

__global__ void __launch_bounds__(256) k_aggHF() {
    const float C0[3] = {0.f, 0.f, 3.f};
    const float C1[3] = {0.f, 3.f, -3.f};
    const float C2[3] = {0.75f, -1.5f, 0.75f};
    int t = blockIdx.x * blockDim.x + threadIdx.x;
    int gi = t >> 4, lane4 = (t & 15) * 4;
    if (gi >= NG) return;
    int fam = gi / NN;
    int node = gi - fam * NN;
    int deg = g_deg[gi];
    const int2* ec = g_ecsr + g_off[gi];
    const float* f = g_L1 + (size_t)fam * NN * HF;
    float4 acc = make_float4(0.f, 0.f, 0.f, 0.f);
    int j = 0;
    for (; j + 4 <= deg; j += 4) {
        int2 e0 = ec[j], e1 = ec[j + 1], e2 = ec[j + 2], e3 = ec[j + 3];
        GACC(e0); GACC(e1); GACC(e2); GACC(e3);
    }
    for (; j < deg; j++) { int2 e = ec[j]; GACC(e); }
    float dv = g_dinv[gi];
    float4 l1 = *(const float4*)(f + (size_t)node * HF + lane4);
    float4 h = *(const float4*)(g_h + (size_t)node * HF + lane4);
    float c0 = C0[fam], c1 = C1[fam], c2 = C2[fam];
    float4 o; float l2;
    l2 = l1.x - dv * acc.x; o.x = c0 * h.x + c1 * l1.x + c2 * l2;
    l2 = l1.y - dv * acc.y; o.y = c0 * h.y + c1 * l1.y + c2 * l2;
    l2 = l1.z - dv * acc.z; o.z = c0 * h.z + c1 * l1.z + c2 * l2;
    l2 = l1.w - dv * acc.w; o.w = c0 * h.w + c1 * l1.w + c2 * l2;
    *(float4*)(g_hf + (size_t)node * HF3 + fam * HF + lane4) = o;
}

// ---------------- GEMM: out = relu(A[M,K] @ W[K,64] + b), f32x2 packed FMA ----
template <int K>
__global__ void __launch_bounds__(256) k_gemm(const float* __restrict__ A, const float* __restrict__ W,
                       const float* __restrict__ bias, float* __restrict__ out, int M) {
    __shared__ float sA[64 * 65];
    __shared__ float sW[64 * 64];
    int tid = threadIdx.x;
    int r2 = tid >> 3;
    int c8 = (tid & 7) * 8;
    int row0 = r2 * 2, row1 = row0 + 1;
    float4 bA = *(const float4*)&bias[c8];
    float4 bB = *(const float4*)&bias[c8 + 4];

    for (int tile = blockIdx.x * 64; tile < M; tile += gridDim.x * 64) {
        ull a00 = 0, a01 = 0, a02 = 0, a03 = 0;
        ull a10 = 0, a11 = 0, a12 = 0, a13 = 0;
        for (int ch = 0; ch < K; ch += 64) {
            __syncthreads();
            #pragma unroll
            for (int idx = tid; idx < 64 * 16; idx += 256) {
                int r = idx >> 4, k4 = idx & 15;
                int gr = tile + r;
                float4 v = make_float4(0.f, 0.f, 0.f, 0.f);
                if (gr < M) v = *(const float4*)&A[(size_t)gr * K + ch + k4 * 4];
                float* p = &sA[r * 65 + k4 * 4];
                p[0] = v.x; p[1] = v.y; p[2] = v.z; p[3] = v.w;
            }
            #pragma unroll
            for (int idx = tid; idx < 64 * 16; idx += 256)
                ((float4*)sW)[idx] = ((const float4*)(W + ch * 64))[idx];
            __syncthreads();
            #pragma unroll 8
            for (int k = 0; k < 64; k++) {
                ull aa0 = packdup(sA[row0 * 65 + k]);
                ull aa1 = packdup(sA[row1 * 65 + k]);
                const float* wr = &sW[k * 64 + c8];
                ulonglong2 wA = *(const ulonglong2*)wr;
                ulonglong2 wB = *(const ulonglong2*)(wr + 4);
                FMA2(a00, aa0, wA.x); FMA2(a01, aa0, wA.y);
                FMA2(a02, aa0, wB.x); FMA2(a03, aa0, wB.y);
                FMA2(a10, aa1, wA.x); FMA2(a11, aa1, wA.y);
                FMA2(a12, aa1, wB.x); FMA2(a13, aa1, wB.y);
            }
        }
        int gr0 = tile + row0, gr1 = tile + row1;
        if (gr0 < M) {
            float2 u0 = unpack2(a00), u1 = unpack2(a01), u2 = unpack2(a02), u3 = unpack2(a03);
            float4 oA, oB;
            oA.x = fmaxf(u0.x + bA.x, 0.f); oA.y = fmaxf(u0.y + bA.y, 0.f);
            oA.z = fmaxf(u1.x + bA.z, 0.f); oA.w = fmaxf(u1.y + bA.w, 0.f);
            oB.x = fmaxf(u2.x + bB.x, 0.f); oB.y = fmaxf(u2.y + bB.y, 0.f);
            oB.z = fmaxf(u3.x + bB.z, 0.f); oB.w = fmaxf(u3.y + bB.w, 0.f);
            *(float4*)&out[(size_t)gr0 * 64 + c8]     = oA;
            *(float4*)&out[(size_t)gr0 * 64 + c8 + 4] = oB;
        }
        if (gr1 < M) {
            float2 u0 = unpack2(a10), u1 = unpack2(a11), u2 = unpack2(a12), u3 = unpack2(a13);
            float4 oA, oB;
            oA.x = fmaxf(u0.x + bA.x, 0.f); oA.y = fmaxf(u0.y + bA.y, 0.f);
            oA.z = fmaxf(u1.x + bA.z, 0.f); oA.w = fmaxf(u1.y + bA.w, 0.f);
            oB.x = fmaxf(u2.x + bB.x, 0.f); oB.y = fmaxf(u2.y + bB.y, 0.f);
            oB.z = fmaxf(u3.x + bB.z, 0.f); oB.w = fmaxf(u3.y + bB.w, 0.f);
            *(float4*)&out[(size_t)gr1 * 64 + c8]     = oA;
            *(float4*)&out[(size_t)gr1 * 64 + c8 + 4] = oB;
        }
    }
}

// ---------------- launch ------------------------------------------------------
extern "C" void kernel_launch(void* const* d_in, const int* in_sizes, int n_in,
                              void* d_out, int out_size) {
    const float* feat = (const float*)d_in[0];
    const float* ep   = (const float*)d_in[1];
    const int*   src  = (const int*)d_in[2];
    const int*   dst  = (const int*)d_in[3];
    const float* W1   = (const float*)d_in[4];
    const float* b1   = (const float*)d_in[5];
    const float* W2   = (const float*)d_in[6];
    const float* b2   = (const float*)d_in[7];
    const float* W3   = (const float*)d_in[8];
    const float* b3   = (const float*)d_in[9];
    float* out = (float*)d_out;
    int E = in_sizes[1];
    int M = NN;

    float *p_h, *p_L1, *p_hf;
    cudaGetSymbolAddress((void**)&p_h,  g_h);
    cudaGetSymbolAddress((void**)&p_L1, g_L1);
    cudaGetSymbolAddress((void**)&p_hf, g_hf);

    int gtiles = (M + 63) / 64;

    // 1) MLP GEMMs first (independent of graph/quantile work)
    k_gemm<128><<<gtiles, 256>>>(feat, W1, b1, p_L1, M);
    k_gemm<64><<<gtiles, 256>>>(p_L1, W2, b2, p_h, M);

    // 2) thresholds via 2-pass 16-bit radix select
    k_init<<<1024, 256>>>();
    k_histA<<<1024, 256>>>(ep, E);
    k_scanA<<<1, 1024>>>();
    k_histB<<<1024, 256>>>(ep, E);
    k_scanB<<<1, 1024>>>();

    // 3) classify + degrees, CSR build (dinv fused into scan3)
    k_classify<<<(E + 255) / 256, 256>>>(ep, dst, E);
    int nscan = (NG + 2047) / 2048;
    k_scan1<<<nscan, 256>>>();
    k_scan2<<<1, 32>>>(nscan);
    k_scan3<<<(NG + 255) / 256, 256>>>();
    k_fill<<<(E + 255) / 256, 256>>>(src, dst, E);

    // 4) Laplacian powers via CSR gather (atomic-free), combines fused
    int agg_blocks = (NG * 16 + 255) / 256;
    k_aggL1<<<agg_blocks, 256>>>();
    k_aggHF<<<agg_blocks, 256>>>();

    // 5) out = relu(hfinal @ W3 + b3)
    k_gemm<192><<<gtiles, 256>>>(p_hf, W3, b3, out, M);
}